// round 9
// baseline (speedup 1.0000x reference)
#include <cuda_runtime.h>
#include <cuda_bf16.h>
#include <mma.h>
#include <cstdint>

using namespace nvcuda;

#define NN    6144
#define INF   256
#define NH    4
#define DHD   64
#define HD    256
#define NCOLS 576

// GEMM tiling (round-6 proven config, frozen)
#define BM 128
#define BN 192
#define BK 64
#define STAGES 3
#define KITERS (NN / BK)     // 96
#define GTHREADS 256

#define A_LD    72
#define B_LD    200
#define A_BYTES (BM * A_LD * 2)          // 18432
#define B_BYTES (BK * B_LD * 2)          // 25600
#define STAGE_BYTES (A_BYTES + 2 * B_BYTES)   // 69632
#define SMEM_BYTES  (STAGES * STAGE_BYTES)    // 208896

// k_pre h-gemm smem layout (dynamic)
#define PXHI 0
#define PXLO 10240
#define PWHI 20480
#define PWLO 37376
#define P_SMEM 54272

// ---------------- scratch ----------------
__device__ float          g_h[NH][NN][DHD];    // RAW h (no bias)
__device__ float          g_esrc[NH][NN];
__device__ float          g_esdst[NH][NN];
__device__ float          g_T[NH][DHD];
__device__ __nv_bfloat16  g_adjb[(size_t)NN * NN];    // 75.5 MB, [m][k]
__device__ __nv_bfloat16  g_Bhi[NN][NCOLS];
__device__ __nv_bfloat16  g_Blo[NN][NCOLS];
__device__ float          g_C[NN][NCOLS];

// ---------------- helpers ----------------
__device__ __forceinline__ uint32_t smem_u32(const void* p) {
    uint32_t a;
    asm("{ .reg .u64 t; cvta.to.shared.u64 t, %1; cvt.u32.u64 %0, t; }" : "=r"(a) : "l"(p));
    return a;
}
__device__ __forceinline__ void cp16(uint32_t dst, const void* src) {
    asm volatile("cp.async.cg.shared.global [%0], [%1], 16;" :: "r"(dst), "l"(src) : "memory");
}
__device__ __forceinline__ uint32_t pack2(int a, int b) {
    return (a > 0 ? 0x3F80u : 0u) | ((b > 0 ? 0x3F80u : 0u) << 16);
}

// ---------------- K1: merged  h = x@W (wmma split, blocks 0..47)  ||  adj->bf16 (rest) ----------------
#define HBLOCKS (NN / 128)         // 48
#define CVTBLKS ((int)((size_t)NN * NN / 2048))   // 18432

__global__ void k_pre(const float* __restrict__ x, const float* __restrict__ W,
                      const int* __restrict__ adj) {
    extern __shared__ char psm[];
    const int bx = blockIdx.x;
    const int tid = threadIdx.x;

    if (bx >= HBLOCKS) {
        // ---- adj int32 -> bf16 ----
        size_t i = (size_t)(bx - HBLOCKS) * 2048 + (size_t)tid * 8;
        const int4* p = (const int4*)(adj + i);
        int4 a = p[0], b = p[1];
        *(uint4*)(&g_adjb[i]) = make_uint4(pack2(a.x, a.y), pack2(a.z, a.w),
                                           pack2(b.x, b.y), pack2(b.z, b.w));
        return;
    }

    // ---- h = x @ W, bf16 3-term split, raw (bias added downstream) ----
    __nv_bfloat16* sXhi = (__nv_bfloat16*)(psm + PXHI);   // [128][40]
    __nv_bfloat16* sXlo = (__nv_bfloat16*)(psm + PXLO);
    __nv_bfloat16* sWhi = (__nv_bfloat16*)(psm + PWHI);   // [32][264]
    __nv_bfloat16* sWlo = (__nv_bfloat16*)(psm + PWLO);

    const int m0 = bx * 128;
    const int wid = tid >> 5;
    const int wm = wid >> 2;         // 0..1 -> 64 rows
    const int wn = wid & 3;          // 0..3 -> head, 64 cols

    wmma::fragment<wmma::accumulator, 16, 16, 16, float> acc[4][4];
#pragma unroll
    for (int r = 0; r < 4; r++)
#pragma unroll
        for (int c = 0; c < 4; c++) wmma::fill_fragment(acc[r][c], 0.f);

    for (int k0 = 0; k0 < INF; k0 += 32) {
        // x tile 128x32 -> split
#pragma unroll
        for (int q = 0; q < 16; q++) {
            int idx = tid + q * 256;
            int m = idx >> 5, kk = idx & 31;
            float v = x[(m0 + m) * INF + k0 + kk];
            __nv_bfloat16 hi = __float2bfloat16(v);
            sXhi[m * 40 + kk] = hi;
            sXlo[m * 40 + kk] = __float2bfloat16(v - __bfloat162float(hi));
        }
        // W tile 32x256 (col = head*64+d) -> split
#pragma unroll
        for (int q = 0; q < 32; q++) {
            int idx = tid + q * 256;
            int kk = idx >> 8, col = idx & 255;
            float v = W[(col >> 6) * (INF * DHD) + (k0 + kk) * DHD + (col & 63)];
            __nv_bfloat16 hi = __float2bfloat16(v);
            sWhi[kk * 264 + col] = hi;
            sWlo[kk * 264 + col] = __float2bfloat16(v - __bfloat162float(hi));
        }
        __syncthreads();
#pragma unroll
        for (int kk2 = 0; kk2 < 2; kk2++) {
            wmma::fragment<wmma::matrix_a, 16, 16, 16, __nv_bfloat16, wmma::row_major> ah[4], al[4];
#pragma unroll
            for (int r = 0; r < 4; r++) {
                wmma::load_matrix_sync(ah[r], sXhi + (wm * 64 + r * 16) * 40 + kk2 * 16, 40);
                wmma::load_matrix_sync(al[r], sXlo + (wm * 64 + r * 16) * 40 + kk2 * 16, 40);
            }
#pragma unroll
            for (int c = 0; c < 4; c++) {
                wmma::fragment<wmma::matrix_b, 16, 16, 16, __nv_bfloat16, wmma::row_major> bh, bl;
                wmma::load_matrix_sync(bh, sWhi + (kk2 * 16) * 264 + wn * 64 + c * 16, 264);
                wmma::load_matrix_sync(bl, sWlo + (kk2 * 16) * 264 + wn * 64 + c * 16, 264);
#pragma unroll
                for (int r = 0; r < 4; r++) {
                    wmma::mma_sync(acc[r][c], ah[r], bh, acc[r][c]);
                    wmma::mma_sync(acc[r][c], ah[r], bl, acc[r][c]);
                    wmma::mma_sync(acc[r][c], al[r], bh, acc[r][c]);
                }
            }
        }
        __syncthreads();
    }
    // store raw h: each warp owns head wn, rows wm*64.., cols c*16..
#pragma unroll
    for (int r = 0; r < 4; r++)
#pragma unroll
        for (int c = 0; c < 4; c++)
            wmma::store_matrix_sync(&g_h[wn][m0 + wm * 64 + r * 16][c * 16],
                                    acc[r][c], DHD, wmma::mem_row_major);
}

// ---------------- K2: scores (bias on load) + init g_T = NN*Wb ----------------
__global__ void k_scores(const float* __restrict__ A, const float* __restrict__ Ab,
                         const float* __restrict__ Wb) {
    const int hd = blockIdx.x;
    if (hd == 0 && blockIdx.y == 0)
        ((float*)g_T)[threadIdx.x] = (float)NN * Wb[threadIdx.x];
    const int wid = threadIdx.x >> 5, lane = threadIdx.x & 31;
    const int n = blockIdx.y * 8 + wid;
    const float h0 = g_h[hd][n][lane]      + Wb[hd * DHD + lane];
    const float h1 = g_h[hd][n][lane + 32] + Wb[hd * DHD + lane + 32];
    const float* Ah = A + hd * 2 * DHD;
    float ps = h0 * Ah[lane] + h1 * Ah[lane + 32];
    float pd = h0 * Ah[64 + lane] + h1 * Ah[96 + lane];
#pragma unroll
    for (int o = 16; o; o >>= 1) {
        ps += __shfl_xor_sync(0xffffffffu, ps, o);
        pd += __shfl_xor_sync(0xffffffffu, pd, o);
    }
    if (lane == 0) {
        g_esrc[hd][n]  = expf(ps + Ab[hd]);
        g_esdst[hd][n] = expf(pd);
    }
}

// ---------------- K3: merged  T-reduce || buildB (bias added) ----------------
#define TBLOCKS 96
#define BBLKS   ((NN * NCOLS) / 256)

__global__ void k_T_buildB(const float* __restrict__ Wb) {
    const int bx = blockIdx.x;
    const int tid = threadIdx.x;

    if (bx < TBLOCKS) {
        const int hd = bx / 24;
        const int base = (bx % 24) * 256;
        const int d = tid & 63, rp = tid >> 6;
        float s = 0.f;
        for (int r = rp; r < 256; r += 4) s += g_h[hd][base + r][d];
        __shared__ float red[256];
        red[tid] = s;
        __syncthreads();
        if (rp == 0)
            atomicAdd(&g_T[hd][d], red[d] + red[64 + d] + red[128 + d] + red[192 + d]);
        return;
    }

    const int idx = (bx - TBLOCKS) * 256 + tid;
    const int k = idx / NCOLS;
    const int col = idx - k * NCOLS;
    float v;
    if (col < 256) {
        int hd = col >> 6, d = col & 63;
        v = g_esdst[hd][k] * (g_h[hd][k][d] + Wb[col]);
    } else if (col < 512) {
        int c2 = col - 256;
        v = g_h[c2 >> 6][k][c2 & 63] + Wb[c2];
    } else if (col < 516) {
        v = g_esdst[col - 512][k];
    } else if (col == 516) {
        v = 1.0f;
    } else {
        v = 0.0f;
    }
    __nv_bfloat16 hi = __float2bfloat16(v);
    float lo = v - __bfloat162float(hi);
    g_Bhi[k][col] = hi;
    g_Blo[k][col] = __float2bfloat16(lo);
}

// ---------------- K4: pipelined wmma GEMM (round-6 frozen) ----------------
__device__ __forceinline__ void load_stage(uint32_t sb, int s, int k0, int m0, int n0,
                                           const __nv_bfloat16* __restrict__ adjb, int tid) {
    const uint32_t a_base  = sb + s * STAGE_BYTES;
    const uint32_t bh_base = a_base + A_BYTES;
    const uint32_t bl_base = bh_base + B_BYTES;
#pragma unroll
    for (int q = 0; q < 4; q++) {
        int idx = tid + q * 256;
        int row = idx >> 3, c = idx & 7;
        cp16(a_base + row * (A_LD * 2) + c * 16,
             adjb + (size_t)(m0 + row) * NN + k0 + c * 8);
    }
#pragma unroll
    for (int q = 0; q < 6; q++) {
        int idx = tid + q * 256;
        int row = idx / 24, c = idx - row * 24;
        cp16(bh_base + row * (B_LD * 2) + c * 16, &g_Bhi[k0 + row][n0 + c * 8]);
    }
#pragma unroll
    for (int q = 0; q < 6; q++) {
        int idx = tid + q * 256;
        int row = idx / 24, c = idx - row * 24;
        cp16(bl_base + row * (B_LD * 2) + c * 16, &g_Blo[k0 + row][n0 + c * 8]);
    }
    asm volatile("cp.async.commit_group;" ::: "memory");
}

__global__ void __launch_bounds__(GTHREADS, 1) k_attn_gemm(const __nv_bfloat16* __restrict__ adjb) {
    extern __shared__ char smem[];
    const uint32_t sb = smem_u32(smem);
    const int tid = threadIdx.x;
    const int wid = tid >> 5;
    const int wm = wid >> 2;          // 0..1  (64 rows each)
    const int wn = wid & 3;           // 0..3  (48 cols each)
    const int n0 = blockIdx.x * BN;
    const int m0 = blockIdx.y * BM;

    wmma::fragment<wmma::accumulator, 16, 16, 16, float> acc[4][3];
#pragma unroll
    for (int r = 0; r < 4; r++)
#pragma unroll
        for (int c = 0; c < 3; c++) wmma::fill_fragment(acc[r][c], 0.f);

    load_stage(sb, 0, 0, m0, n0, adjb, tid);
    load_stage(sb, 1, BK, m0, n0, adjb, tid);

    for (int i = 0; i < KITERS; i++) {
        const int s = i % STAGES;

        asm volatile("cp.async.wait_group 1;" ::: "memory");
        __syncthreads();
        if (i + 2 < KITERS)
            load_stage(sb, (i + 2) % STAGES, (i + 2) * BK, m0, n0, adjb, tid);
        else
            asm volatile("cp.async.commit_group;" ::: "memory");

        const __nv_bfloat16* sA  = (const __nv_bfloat16*)(smem + s * STAGE_BYTES);
        const __nv_bfloat16* sBh = (const __nv_bfloat16*)(smem + s * STAGE_BYTES + A_BYTES);
        const __nv_bfloat16* sBl = (const __nv_bfloat16*)(smem + s * STAGE_BYTES + A_BYTES + B_BYTES);

#pragma unroll
        for (int kk = 0; kk < BK / 16; kk++) {
            wmma::fragment<wmma::matrix_a, 16, 16, 16, __nv_bfloat16, wmma::row_major> af[4];
#pragma unroll
            for (int r = 0; r < 4; r++)
                wmma::load_matrix_sync(af[r], sA + (wm * 64 + r * 16) * A_LD + kk * 16, A_LD);
#pragma unroll
            for (int c = 0; c < 3; c++) {
                wmma::fragment<wmma::matrix_b, 16, 16, 16, __nv_bfloat16, wmma::row_major> bf;
                wmma::load_matrix_sync(bf, sBh + (kk * 16) * B_LD + wn * 48 + c * 16, B_LD);
#pragma unroll
                for (int r = 0; r < 4; r++) wmma::mma_sync(acc[r][c], af[r], bf, acc[r][c]);
                wmma::load_matrix_sync(bf, sBl + (kk * 16) * B_LD + wn * 48 + c * 16, B_LD);
#pragma unroll
                for (int r = 0; r < 4; r++) wmma::mma_sync(acc[r][c], af[r], bf, acc[r][c]);
            }
        }
    }

#pragma unroll
    for (int r = 0; r < 4; r++)
#pragma unroll
        for (int c = 0; c < 3; c++)
            wmma::store_matrix_sync(&g_C[m0 + wm * 64 + r * 16][n0 + wn * 48 + c * 16],
                                    acc[r][c], NCOLS, wmma::mem_row_major);
}

// ---------------- K5: epilogue ----------------
__global__ void k_epi(float* __restrict__ out) {
    const int idx = blockIdx.x * 256 + threadIdx.x;
    const int n = idx >> 8;
    const int c = idx & 255;
    const int hd = c >> 6, d = c & 63;
    const float es  = g_esrc[hd][n];
    const float u   = g_C[n][hd * 64 + d];
    const float v   = g_C[n][256 + hd * 64 + d];
    const float w   = g_C[n][512 + hd];
    const float deg = g_C[n][516];
    const float Z = es * w + ((float)NN - deg);
    out[idx] = (es * u + g_T[hd][d] - v) / Z;
}

// ---------------- launch ----------------
extern "C" void kernel_launch(void* const* d_in, const int* in_sizes, int n_in,
                              void* d_out, int out_size) {
    const float* x = nullptr; const int* adj = nullptr;
    const float* W = nullptr; const float* Wb = nullptr;
    const float* A = nullptr; const float* Ab = nullptr;
    for (int i = 0; i < n_in; i++) {
        switch (in_sizes[i]) {
            case NN * INF:        x   = (const float*)d_in[i]; break;
            case NH * INF * DHD:  W   = (const float*)d_in[i]; break;
            case NH * DHD:        Wb  = (const float*)d_in[i]; break;
            case NH * 2 * DHD:    A   = (const float*)d_in[i]; break;
            case NH:              Ab  = (const float*)d_in[i]; break;
            default:
                if (in_sizes[i] == NN * NN) adj = (const int*)d_in[i];
                break;
        }
    }
    float* out = (float*)d_out;

    cudaFuncSetAttribute(k_attn_gemm, cudaFuncAttributeMaxDynamicSharedMemorySize, SMEM_BYTES);
    cudaFuncSetAttribute(k_pre, cudaFuncAttributeMaxDynamicSharedMemorySize, P_SMEM);

    __nv_bfloat16* adjb_ptr = nullptr;
    cudaGetSymbolAddress((void**)&adjb_ptr, g_adjb);

    k_pre<<<HBLOCKS + CVTBLKS, 256, P_SMEM>>>(x, W, adj);
    k_scores<<<dim3(NH, NN / 8), 256>>>(A, Ab, Wb);
    k_T_buildB<<<TBLOCKS + BBLKS, 256>>>(Wb);
    k_attn_gemm<<<dim3(NCOLS / BN, NN / BM), GTHREADS, SMEM_BYTES>>>(adjb_ptr);
    k_epi<<<(NN * HD) / 256, 256>>>(out);
}